// round 12
// baseline (speedup 1.0000x reference)
#include <cuda_runtime.h>
#include <cuda_fp16.h>
#include <cstdint>

// x:(8,256,16384) f32, w:(256,64,13) f32, b:(256) f32 -> out:(8,256,16384) f32
// M=5,N=2 -> U=3, GROUPS=4, DIL=2.  Both DIL phases handled by one CTA.
#define TI      8192
#define TFULL   16384
#define TSTRIDE 60
#define NT      137                // ceil(8192/60)
#define XR      68
#define XPW     40                 // x row pitch (words)
#define BPW     40                 // B row pitch (words)
#define BROWS   192
#define BCHUNK  (BROWS * BPW * 4)  // 30720 B per tap (fp16 pairs)
#define BCH16   (BCHUNK / 16)      // 1920 uint4 per tap
#define EPITCH  195                // stride mod 32 = 3 -> conflict-free epilogue
#define BOUND   1.41421356237309515f

// smem layout (bytes): x tiles (phase 0, phase 1), then 2 double-buffered B slots
#define X_OFF(ph) ((ph) * XR * XPW * 4)             // 0 / 10880
#define B_OFF(s)  ((2 * XR * XPW * 4) + (s) * BCHUNK)  // 21760 + s*30720
#define SMEMSZ    (2 * XR * XPW * 4 + 2 * BCHUNK)      // 83200 ; epilogue 64x195 f32 = 49920 overlays

// Pre-swizzled packed weights: [g][tap] blocks of 192 rows x 40 words (fp16 pairs)
__device__ uint4 g_wB[4 * 5 * BCH16];

__device__ __forceinline__ int swz(int r) { return (r & 3) ^ ((r >> 2) & 3); }

__device__ __forceinline__ uint32_t smem_u32(const void* p) {
    uint32_t a;
    asm("{ .reg .u64 t; cvta.to.shared.u64 t, %1; cvt.u32.u64 %0, t; }" : "=r"(a) : "l"(p));
    return a;
}
__device__ __forceinline__ uint2 lds64(uint32_t addr) {
    uint2 v;
    asm volatile("ld.shared.v2.b32 {%0,%1}, [%2];" : "=r"(v.x), "=r"(v.y) : "r"(addr));
    return v;
}
__device__ __forceinline__ void cp16(uint32_t dst, const void* src) {
    asm volatile("cp.async.cg.shared.global [%0], [%1], 16;" :: "r"(dst), "l"(src) : "memory");
}
#define CP_COMMIT() asm volatile("cp.async.commit_group;" ::: "memory")
#define CP_WAIT(n)  asm volatile("cp.async.wait_group %0;" :: "n"(n) : "memory")

__device__ __forceinline__ void mma16816(float* c, uint32_t a0, uint32_t a1,
                                         uint32_t a2, uint32_t a3,
                                         uint32_t b0, uint32_t b1) {
    asm volatile(
        "mma.sync.aligned.m16n8k16.row.col.f32.f16.f16.f32 "
        "{%0,%1,%2,%3}, {%4,%5,%6,%7}, {%8,%9}, {%0,%1,%2,%3};"
        : "+f"(c[0]), "+f"(c[1]), "+f"(c[2]), "+f"(c[3])
        : "r"(a0), "r"(a1), "r"(a2), "r"(a3), "r"(b0), "r"(b1));
}

// ---------------- weight prep: fused filters, fp16, swizzled image ----------------
//  t0:  wc[j] = w[3j]
//  d1:  [-w2, w2-w5, w5-w8, w8-w11, w11]
//  d2:  [-w1, w1-w4, w4-w7, w7-w10, w10]
__global__ void pack_w(const float* __restrict__ w) {
    int o = blockIdx.x;      // 0..255
    int c = threadIdx.x;     // 0..63
    int g = o >> 6, oo = o & 63;
    const float* ws = w + ((size_t)o * 64 + c) * 13;
    float f[3][5];
    #pragma unroll
    for (int j = 0; j < 5; j++) f[0][j] = ws[3 * j];
    f[1][0] = -ws[2];  f[1][1] = ws[2] - ws[5];  f[1][2] = ws[5] - ws[8];
    f[1][3] = ws[8] - ws[11];  f[1][4] = ws[11];
    f[2][0] = -ws[1];  f[2][1] = ws[1] - ws[4];  f[2][2] = ws[4] - ws[7];
    f[2][3] = ws[7] - ws[10];  f[2][4] = ws[10];

    int wl  = c >> 1;
    int q   = wl & 3, hi = (wl >> 2) & 1, cblk = wl >> 3;
    int sub = c & 1;
    char* base = (char*)g_wB;
    #pragma unroll
    for (int fi = 0; fi < 3; fi++) {
        int n = fi * 64 + oo;
        int pw = cblk * 8 + 2 * (q ^ swz(n)) + hi;
        size_t rowoff = (size_t)n * BPW * 4 + (size_t)pw * 4 + sub * 2;
        #pragma unroll
        for (int j = 0; j < 5; j++) {
            size_t blk = (size_t)(g * 5 + j) * BCHUNK;
            *(__half*)(base + blk + rowoff) = __float2half_rn(f[fi][j]);
        }
    }
}

// ---------------- main kernel ----------------
// grid (137, 8, 4), 256 threads, 2 CTAs/SM. One CTA = both DIL phases of a tile.
// Warp (wm = wid&1, wn = wid>>1): rows wm*32..+31 of 64, cols wn*48..+47 of 192.
__global__ void __launch_bounds__(256, 2) pconv_mma(
    const float* __restrict__ x, const float* __restrict__ bias, float* __restrict__ out)
{
    extern __shared__ char smem[];
    const uint32_t sb = smem_u32(smem);
    const int tid = threadIdx.x, lane = tid & 31, wid = tid >> 5;
    const int wm = wid & 1, wn = wid >> 1;
    const int q = lane & 3, ls = lane >> 2;
    const int tbase = blockIdx.x * TSTRIDE;
    const int batch = blockIdx.y;
    const int g = blockIdx.z;

    const uint4* wB = g_wB + (size_t)g * 5 * BCH16;

    // prologue: async-copy tap 0 into slot 0 (overlaps x staging)
    {
        const char* src = (const char*)wB;
        for (int idx = tid; idx < BCH16; idx += 256)
            cp16(sb + B_OFF(0) + idx * 16, src + idx * 16);
        CP_COMMIT();
    }

    // ---- stage x tiles, BOTH phases: rows p = tbase-4+m, coalesced float2 LDG ----
    {
        uint32_t* xw0 = (uint32_t*)(smem + X_OFF(0));
        uint32_t* xw1 = (uint32_t*)(smem + X_OFF(1));
        const float* xg = x + ((size_t)batch * 256 + (size_t)g * 64) * TFULL;
        const int i0 = wid;          // channel-pair base 0..7
        const int ml = lane;
        #pragma unroll
        for (int ib = 0; ib < 4; ib++) {
            int i = i0 + ib * 8;     // channel pair 0..31
            int iq = i & 3, ih = (i >> 2) & 1, icb = i >> 3;
            const float* xr0 = xg + (size_t)(2 * i) * TFULL;
            const float* xr1 = xg + (size_t)(2 * i + 1) * TFULL;
            #pragma unroll
            for (int mb = 0; mb < 3; mb++) {
                int m = ml + mb * 32;
                if (m >= XR) break;
                int p = tbase - 4 + m;
                float2 v0 = make_float2(0.f, 0.f), v1 = make_float2(0.f, 0.f);
                if (p >= 0 && p < TI) {
                    v0 = *(const float2*)&xr0[2 * (size_t)p];   // {phase0, phase1} ch 2i
                    v1 = *(const float2*)&xr1[2 * (size_t)p];   // {phase0, phase1} ch 2i+1
                }
                int pw = icb * 8 + 2 * (iq ^ swz(m)) + ih;
                xw0[m * XPW + pw] = (uint32_t)__half_as_ushort(__float2half_rn(v0.x))
                                  | ((uint32_t)__half_as_ushort(__float2half_rn(v1.x)) << 16);
                xw1[m * XPW + pw] = (uint32_t)__half_as_ushort(__float2half_rn(v0.y))
                                  | ((uint32_t)__half_as_ushort(__float2half_rn(v1.y)) << 16);
            }
        }
    }

    float acc[2][2][6][4];   // [phase][mi][ni][k]
    #pragma unroll
    for (int ph = 0; ph < 2; ph++)
        #pragma unroll
        for (int mi = 0; mi < 2; mi++)
            #pragma unroll
            for (int ni = 0; ni < 6; ni++)
                #pragma unroll
                for (int k = 0; k < 4; k++) acc[ph][mi][ni][k] = 0.f;

    // B fragment offsets are tap-invariant
    uint32_t bofs[6];
    #pragma unroll
    for (int ni = 0; ni < 6; ni++) {
        int n = wn * 48 + ni * 8 + ls;
        bofs[ni] = (uint32_t)(n * BPW + 2 * (q ^ swz(n))) * 4;
    }

    #pragma unroll
    for (int j = 0; j < 5; j++) {
        if (j < 4) {   // prefetch tap j+1 into the other slot
            const char* src = (const char*)(wB + (size_t)(j + 1) * BCH16);
            uint32_t dst = sb + B_OFF((j + 1) & 1);
            for (int idx = tid; idx < BCH16; idx += 256)
                cp16(dst + idx * 16, src + idx * 16);
            CP_COMMIT();
            CP_WAIT(1);
        } else {
            CP_WAIT(0);
        }
        __syncthreads();   // tap j visible; x tiles ready (j==0)

        const uint32_t bb = sb + B_OFF(j & 1);
        #pragma unroll
        for (int cblk = 0; cblk < 4; cblk++) {
            uint2 bh[6];
            #pragma unroll
            for (int ni = 0; ni < 6; ni++)
                bh[ni] = lds64(bb + bofs[ni] + cblk * 32);

            uint32_t awoff[2][2];
            #pragma unroll
            for (int mi = 0; mi < 2; mi++)
                #pragma unroll
                for (int ro = 0; ro < 2; ro++) {
                    int r = wm * 32 + mi * 16 + ls + j + ro * 8;
                    awoff[mi][ro] = (uint32_t)(r * XPW + cblk * 8 + 2 * (q ^ swz(r))) * 4;
                }

            #pragma unroll
            for (int ph = 0; ph < 2; ph++) {
                const uint32_t xb = sb + X_OFF(ph);
                uint2 a[2][2];
                #pragma unroll
                for (int mi = 0; mi < 2; mi++)
                    #pragma unroll
                    for (int ro = 0; ro < 2; ro++)
                        a[mi][ro] = lds64(xb + awoff[mi][ro]);
                #pragma unroll
                for (int ni = 0; ni < 6; ni++) {
                    mma16816(acc[ph][0][ni], a[0][0].x, a[0][1].x, a[0][0].y, a[0][1].y, bh[ni].x, bh[ni].y);
                    mma16816(acc[ph][1][ni], a[1][0].x, a[1][1].x, a[1][0].y, a[1][1].y, bh[ni].x, bh[ni].y);
                }
            }
        }
        __syncthreads();   // slot (j&1) reads done before overwrite at j+2
    }

    // ---- epilogue: two passes over one 64x195 f32 buffer (overlays stage smem) ----
    float* eb = (float*)smem;
    const bool interior = (blockIdx.x > 0) && (blockIdx.x < NT - 1);
    float* outg = out + ((size_t)batch * 256 + (size_t)g * 64) * TFULL;
    float rker[2][8][2];   // [phase][ko][rb] results held in registers

    #pragma unroll
    for (int ph = 0; ph < 2; ph++) {
        __syncthreads();   // prior eb readers (or mainloop) done
        #pragma unroll
        for (int mi = 0; mi < 2; mi++) {
            int r0 = wm * 32 + mi * 16 + ls;
            #pragma unroll
            for (int ni = 0; ni < 6; ni++) {
                int col = wn * 48 + ni * 8 + q * 2;
                eb[r0 * EPITCH + col]           = acc[ph][mi][ni][0];
                eb[r0 * EPITCH + col + 1]       = acc[ph][mi][ni][1];
                eb[(r0 + 8) * EPITCH + col]     = acc[ph][mi][ni][2];
                eb[(r0 + 8) * EPITCH + col + 1] = acc[ph][mi][ni][3];
            }
        }
        __syncthreads();

        #pragma unroll
        for (int ko = 0; ko < 8; ko++) {
            int o = wid * 8 + ko;
            float bv = __ldg(&bias[g * 64 + o]);
            #pragma unroll
            for (int rb = 0; rb < 2; rb++) {
                int m = 2 + rb * 32 + lane;
                float r = 0.f;
                if (m <= 61) {
                    int t = tbase + m - 2;
                    if (interior) {
                        float s0 = eb[(m - 2) * EPITCH + o] + bv;
                        float s1 = eb[(m - 1) * EPITCH + o] + bv;
                        float s2 = eb[m * EPITCH + o] + bv;
                        float s3 = eb[(m + 1) * EPITCH + o] + bv;
                        float s4 = eb[(m + 2) * EPITCH + o] + bv;
                        float mean = (s0 + s1 + s2 + s3 + s4) * 0.2f;
                        float den = fminf(fmaxf(s2 - mean, 1.0f), BOUND);
                        float y = fmaf(den, -0.70710678f, 1.6944272f);
                        y = y * (2.0f - den * y);
                        y = y * (2.0f - den * y);
                        float d1 = eb[m * EPITCH + 64 + o];
                        float d2 = eb[m * EPITCH + 128 + o];
                        r = 0.25f * (s2 + (d1 + d2) * y + 2.0f * (d2 - d1) * y * y);
                    } else if (t < TI) {
                        float s[5];
                        #pragma unroll
                        for (int d = 0; d < 5; d++) {
                            int rm = m - 2 + d;
                            int tr = tbase + rm - 2;
                            float v = eb[rm * EPITCH + o] + bv;
                            s[d] = (tr >= 2 && tr < TI - 2) ? v : 0.f;
                        }
                        float mean = (s[0] + s[1] + s[2] + s[3] + s[4]) * 0.2f;
                        float den = fminf(fmaxf(s[2] - mean, 1.0f), BOUND);
                        float y = fmaf(den, -0.70710678f, 1.6944272f);
                        y = y * (2.0f - den * y);
                        y = y * (2.0f - den * y);
                        bool cv = (t >= 2) && (t < TI - 2);
                        float d1 = cv ? eb[m * EPITCH + 64 + o]  : 0.f;
                        float d2 = cv ? eb[m * EPITCH + 128 + o] : 0.f;
                        r = 0.25f * (s[2] + (d1 + d2) * y + 2.0f * (d2 - d1) * y * y);
                    }
                }
                rker[ph][ko][rb] = r;
            }
        }
    }

    // ---- coalesced float2 stores: {phase0, phase1} are adjacent in gmem ----
    #pragma unroll
    for (int ko = 0; ko < 8; ko++) {
        int o = wid * 8 + ko;
        float* op = outg + (size_t)o * TFULL;
        #pragma unroll
        for (int rb = 0; rb < 2; rb++) {
            int m = 2 + rb * 32 + lane;
            if (m > 61) continue;
            int t = tbase + m - 2;
            if (t >= TI) continue;
            *(float2*)&op[2 * (size_t)t] = make_float2(rker[0][ko][rb], rker[1][ko][rb]);
        }
    }
}

extern "C" void kernel_launch(void* const* d_in, const int* in_sizes, int n_in,
                              void* d_out, int out_size)
{
    const float* x = (const float*)d_in[0];
    const float* w = (const float*)d_in[1];
    const float* b = (const float*)d_in[2];
    float* out = (float*)d_out;

    pack_w<<<256, 64>>>(w);

    cudaFuncSetAttribute(pconv_mma, cudaFuncAttributeMaxDynamicSharedMemorySize, SMEMSZ);
    dim3 grid(NT, 8, 4);
    pconv_mma<<<grid, 256, SMEMSZ>>>(x, b, out);
}

// round 13
// speedup vs baseline: 1.1682x; 1.1682x over previous
#include <cuda_runtime.h>
#include <cuda_fp16.h>
#include <cstdint>

// x:(8,256,16384) f32, w:(256,64,13) f32, b:(256) f32 -> out:(8,256,16384) f32
// M=5,N=2 -> U=3, GROUPS=4, DIL=2
#define TI      8192
#define TFULL   16384
#define TSTRIDE 60
#define NT      137                // ceil(8192/60)
#define XR      68
#define XPW     40                 // x row pitch (words)
#define EPITCH  195                // stride mod 32 = 3 -> conflict-free epilogue
#define BOUND   1.41421356237309515f

// B gmem image: lane-contiguous fragments.
// [g][tap j][cblk][wn][lane][ni] -> uint2 fragment (48 B per lane per (j,cblk,wn))
#define B_PER_JC   (4 * 32 * 48)          // per (j,cblk): 4 wn x 32 lanes x 48B = 6144
#define B_PER_J    (4 * B_PER_JC)         // 24576
#define B_PER_G    (5 * B_PER_J)          // 122880
__device__ uint4 g_wB[4 * B_PER_G / 16];

// smem: epilogue buffer 64 x 195 f32 (x stage tile overlays offset 0)
#define SMEMSZ (64 * EPITCH * 4)          // 49920

__device__ __forceinline__ int swz(int r) { return (r & 3) ^ ((r >> 2) & 3); }

__device__ __forceinline__ uint32_t smem_u32(const void* p) {
    uint32_t a;
    asm("{ .reg .u64 t; cvta.to.shared.u64 t, %1; cvt.u32.u64 %0, t; }" : "=r"(a) : "l"(p));
    return a;
}
__device__ __forceinline__ uint2 lds64(uint32_t addr) {
    uint2 v;
    asm volatile("ld.shared.v2.b32 {%0,%1}, [%2];" : "=r"(v.x), "=r"(v.y) : "r"(addr));
    return v;
}
__device__ __forceinline__ void mma16816(float* c, uint32_t a0, uint32_t a1,
                                         uint32_t a2, uint32_t a3,
                                         uint32_t b0, uint32_t b1) {
    asm volatile(
        "mma.sync.aligned.m16n8k16.row.col.f32.f16.f16.f32 "
        "{%0,%1,%2,%3}, {%4,%5,%6,%7}, {%8,%9}, {%0,%1,%2,%3};"
        : "+f"(c[0]), "+f"(c[1]), "+f"(c[2]), "+f"(c[3])
        : "r"(a0), "r"(a1), "r"(a2), "r"(a3), "r"(b0), "r"(b1));
}

// ---------------- weight prep: fused filters, fp16, lane-contiguous fragments ----
//  t0:  wc[j] = w[3j]
//  d1:  [-w2, w2-w5, w5-w8, w8-w11, w11]
//  d2:  [-w1, w1-w4, w4-w7, w7-w10, w10]
__global__ void pack_w(const float* __restrict__ w) {
    int o = blockIdx.x;      // 0..255
    int c = threadIdx.x;     // 0..63 (input channel within group)
    int g = o >> 6, oo = o & 63;
    const float* ws = w + ((size_t)o * 64 + c) * 13;
    float f[3][5];
    #pragma unroll
    for (int j = 0; j < 5; j++) f[0][j] = ws[3 * j];
    f[1][0] = -ws[2];  f[1][1] = ws[2] - ws[5];  f[1][2] = ws[5] - ws[8];
    f[1][3] = ws[8] - ws[11];  f[1][4] = ws[11];
    f[2][0] = -ws[1];  f[2][1] = ws[1] - ws[4];  f[2][2] = ws[4] - ws[7];
    f[2][3] = ws[7] - ws[10];  f[2][4] = ws[10];

    // channel c -> (cblk, q, hi, sub); mma b-frag word hi at k-word wl = cblk*8 + hi*4 + q
    int wl = c >> 1, sub = c & 1;
    int q = wl & 3, hi = (wl >> 2) & 1, cblk = wl >> 3;
    char* base = (char*)g_wB + (size_t)g * B_PER_G;
    #pragma unroll
    for (int fi = 0; fi < 3; fi++) {
        int n = fi * 64 + oo;            // B row 0..191
        int wn = n / 48;
        int rem = n - wn * 48;
        int ni = rem >> 3, ls = rem & 7;
        int lane = ls * 4 + q;
        size_t off = (size_t)cblk * B_PER_JC + (size_t)wn * (32 * 48)
                   + (size_t)lane * 48 + ni * 8 + hi * 4 + sub * 2;
        #pragma unroll
        for (int j = 0; j < 5; j++)
            *(__half*)(base + (size_t)j * B_PER_J + off) = __float2half_rn(f[fi][j]);
    }
}

// ---------------- main kernel ----------------
// grid (137, 16, 4), 256 threads, 3 CTAs/SM. Per-phase CTAs.
// Warp (wm = wid&1, wn = wid>>1): rows wm*32..+31 of 64, cols wn*48..+47 of 192.
// Tile row m <-> t = tbase + m - 2; A[m,(j,c)] = xs[tbase + m - 4 + j][c].
__global__ void __launch_bounds__(256, 3) pconv_mma(
    const float* __restrict__ x, const float* __restrict__ bias, float* __restrict__ out)
{
    extern __shared__ char smem[];
    const uint32_t sb = smem_u32(smem);
    const int tid = threadIdx.x, lane = tid & 31, wid = tid >> 5;
    const int wm = wid & 1, wn = wid >> 1;
    const int q = lane & 3, ls = lane >> 2;
    const int tbase = blockIdx.x * TSTRIDE;
    const int batch = blockIdx.y >> 1, phase = blockIdx.y & 1;
    const int g = blockIdx.z;

    // per-lane B base pointer (lane-contiguous 48B fragments)
    const char* bp0 = (const char*)g_wB + (size_t)g * B_PER_G
                    + (size_t)wn * (32 * 48) + (size_t)lane * 48;

    // ---- stage x tile: rows p = tbase-4+m, fp16, swizzled pair layout ----
    {
        uint32_t* xw = (uint32_t*)smem;
        const float* xg = x + ((size_t)batch * 256 + (size_t)g * 64) * TFULL + phase;
        const int i0 = wid;          // channel-pair base 0..7
        const int ml = lane;
        #pragma unroll
        for (int ib = 0; ib < 4; ib++) {
            int i = i0 + ib * 8;     // channel pair 0..31
            int iq = i & 3, ih = (i >> 2) & 1, icb = i >> 3;
            const float* xr0 = xg + (size_t)(2 * i) * TFULL;
            const float* xr1 = xg + (size_t)(2 * i + 1) * TFULL;
            #pragma unroll
            for (int mb = 0; mb < 3; mb++) {
                int m = ml + mb * 32;
                if (m >= XR) break;
                int p = tbase - 4 + m;
                float v0 = 0.f, v1 = 0.f;
                if (p >= 0 && p < TI) {
                    v0 = xr0[2 * (size_t)p];
                    v1 = xr1[2 * (size_t)p];
                }
                __half h0 = __float2half_rn(v0), h1 = __float2half_rn(v1);
                int pw = icb * 8 + 2 * (iq ^ swz(m)) + ih;
                xw[m * XPW + pw] = (uint32_t)__half_as_ushort(h0)
                                 | ((uint32_t)__half_as_ushort(h1) << 16);
            }
        }
    }

    float acc[2][6][4];
    #pragma unroll
    for (int mi = 0; mi < 2; mi++)
        #pragma unroll
        for (int ni = 0; ni < 6; ni++)
            #pragma unroll
            for (int k = 0; k < 4; k++) acc[mi][ni][k] = 0.f;

    __syncthreads();   // x tile visible; mainloop is sync-free

    #pragma unroll
    for (int j = 0; j < 5; j++) {
        #pragma unroll
        for (int cblk = 0; cblk < 4; cblk++) {
            // B fragments: 3 x LDG.128 = 6 uint2 frags (L1-resident image)
            const uint4* bp = (const uint4*)(bp0 + (size_t)j * B_PER_J
                                                 + (size_t)cblk * B_PER_JC);
            uint4 u0 = __ldg(bp);
            uint4 u1 = __ldg(bp + 1);
            uint4 u2 = __ldg(bp + 2);

            uint2 a[2][2];
            #pragma unroll
            for (int mi = 0; mi < 2; mi++)
                #pragma unroll
                for (int ro = 0; ro < 2; ro++) {
                    int r = wm * 32 + mi * 16 + ls + j + ro * 8;
                    uint32_t woff = (uint32_t)(r * XPW + cblk * 8 + 2 * (q ^ swz(r))) * 4;
                    a[mi][ro] = lds64(sb + woff);
                }

            #pragma unroll
            for (int mi = 0; mi < 2; mi++) {
                mma16816(acc[mi][0], a[mi][0].x, a[mi][1].x, a[mi][0].y, a[mi][1].y, u0.x, u0.y);
                mma16816(acc[mi][1], a[mi][0].x, a[mi][1].x, a[mi][0].y, a[mi][1].y, u0.z, u0.w);
                mma16816(acc[mi][2], a[mi][0].x, a[mi][1].x, a[mi][0].y, a[mi][1].y, u1.x, u1.y);
                mma16816(acc[mi][3], a[mi][0].x, a[mi][1].x, a[mi][0].y, a[mi][1].y, u1.z, u1.w);
                mma16816(acc[mi][4], a[mi][0].x, a[mi][1].x, a[mi][0].y, a[mi][1].y, u2.x, u2.y);
                mma16816(acc[mi][5], a[mi][0].x, a[mi][1].x, a[mi][0].y, a[mi][1].y, u2.z, u2.w);
            }
        }
    }

    // ---- epilogue: dump acc -> smem [64][195] f32 (overlays x tile) ----
    __syncthreads();
    float* eb = (float*)smem;
    #pragma unroll
    for (int mi = 0; mi < 2; mi++) {
        int r0 = wm * 32 + mi * 16 + ls;
        #pragma unroll
        for (int ni = 0; ni < 6; ni++) {
            int col = wn * 48 + ni * 8 + q * 2;
            eb[r0 * EPITCH + col]           = acc[mi][ni][0];
            eb[r0 * EPITCH + col + 1]       = acc[mi][ni][1];
            eb[(r0 + 8) * EPITCH + col]     = acc[mi][ni][2];
            eb[(r0 + 8) * EPITCH + col + 1] = acc[mi][ni][3];
        }
    }
    __syncthreads();

    const bool interior = (blockIdx.x > 0) && (blockIdx.x < NT - 1);
    float* outg = out + ((size_t)batch * 256 + (size_t)g * 64) * TFULL + phase;

    if (interior) {
        #pragma unroll 1
        for (int ko = 0; ko < 8; ko++) {
            int o = wid * 8 + ko;
            float bv = __ldg(&bias[g * 64 + o]);
            float* op = outg + (size_t)o * TFULL;
            #pragma unroll
            for (int rb = 0; rb < 2; rb++) {
                int m = 2 + rb * 32 + lane;
                if (m > 61) continue;
                int t = tbase + m - 2;
                float s0 = eb[(m - 2) * EPITCH + o] + bv;
                float s1 = eb[(m - 1) * EPITCH + o] + bv;
                float s2 = eb[m * EPITCH + o] + bv;
                float s3 = eb[(m + 1) * EPITCH + o] + bv;
                float s4 = eb[(m + 2) * EPITCH + o] + bv;
                float mean = (s0 + s1 + s2 + s3 + s4) * 0.2f;
                float den = fminf(fmaxf(s2 - mean, 1.0f), BOUND);
                float y = fmaf(den, -0.70710678f, 1.6944272f);
                y = y * (2.0f - den * y);
                y = y * (2.0f - den * y);
                float d1 = eb[m * EPITCH + 64 + o];
                float d2 = eb[m * EPITCH + 128 + o];
                float r = 0.25f * (s2 + (d1 + d2) * y + 2.0f * (d2 - d1) * y * y);
                op[2 * (size_t)t] = r;
            }
        }
    } else {
        #pragma unroll 1
        for (int ko = 0; ko < 8; ko++) {
            int o = wid * 8 + ko;
            float bv = __ldg(&bias[g * 64 + o]);
            float* op = outg + (size_t)o * TFULL;
            #pragma unroll 1
            for (int rb = 0; rb < 2; rb++) {
                int m = 2 + rb * 32 + lane;
                if (m > 61) continue;
                int t = tbase + m - 2;
                if (t >= TI) continue;
                float s[5];
                #pragma unroll
                for (int d = 0; d < 5; d++) {
                    int rm = m - 2 + d;
                    int tr = tbase + rm - 2;
                    float v = eb[rm * EPITCH + o] + bv;
                    s[d] = (tr >= 2 && tr < TI - 2) ? v : 0.f;
                }
                float mean = (s[0] + s[1] + s[2] + s[3] + s[4]) * 0.2f;
                float den = fminf(fmaxf(s[2] - mean, 1.0f), BOUND);
                float y = fmaf(den, -0.70710678f, 1.6944272f);
                y = y * (2.0f - den * y);
                y = y * (2.0f - den * y);
                bool cv = (t >= 2) && (t < TI - 2);
                float d1 = cv ? eb[m * EPITCH + 64 + o]  : 0.f;
                float d2 = cv ? eb[m * EPITCH + 128 + o] : 0.f;
                float r = 0.25f * (s[2] + (d1 + d2) * y + 2.0f * (d2 - d1) * y * y);
                op[2 * (size_t)t] = r;
            }
        }
    }
}

extern "C" void kernel_launch(void* const* d_in, const int* in_sizes, int n_in,
                              void* d_out, int out_size)
{
    const float* x = (const float*)d_in[0];
    const float* w = (const float*)d_in[1];
    const float* b = (const float*)d_in[2];
    float* out = (float*)d_out;

    pack_w<<<256, 64>>>(w);

    cudaFuncSetAttribute(pconv_mma, cudaFuncAttributeMaxDynamicSharedMemorySize, SMEMSZ);
    dim3 grid(NT, 16, 4);
    pconv_mma<<<grid, 256, SMEMSZ>>>(x, b, out);
}

// round 14
// speedup vs baseline: 1.1748x; 1.0057x over previous
#include <cuda_runtime.h>
#include <cuda_fp16.h>
#include <cstdint>

// x:(8,256,16384) f32, w:(256,64,13) f32, b:(256) f32 -> out:(8,256,16384) f32
// M=5,N=2 -> U=3, GROUPS=4, DIL=2
#define TI      8192
#define TFULL   16384
#define TSTRIDE 60
#define NT      137                // ceil(8192/60)
#define XR      68
#define XPW     40                 // x row pitch (words)
#define EPITCH  195                // stride mod 32 = 3 -> conflict-free epilogue
#define BOUND   1.41421356237309515f

// B gmem image: lane-contiguous fragments.
// [g][tap j][cblk][wn][lane][ni] -> uint2 fragment (48 B per lane per (j,cblk,wn))
#define B_PER_JC   (4 * 32 * 48)          // per (j,cblk): 4 wn x 32 lanes x 48B = 6144
#define B_PER_J    (4 * B_PER_JC)         // 24576
#define B_PER_G    (5 * B_PER_J)          // 122880
__device__ uint4 g_wB[4 * B_PER_G / 16];

// smem: epilogue buffer 64 x 195 f32 (x stage tile overlays offset 0)
#define SMEMSZ (64 * EPITCH * 4)          // 49920

__device__ __forceinline__ int swz(int r) { return (r & 3) ^ ((r >> 2) & 3); }

__device__ __forceinline__ uint32_t smem_u32(const void* p) {
    uint32_t a;
    asm("{ .reg .u64 t; cvta.to.shared.u64 t, %1; cvt.u32.u64 %0, t; }" : "=r"(a) : "l"(p));
    return a;
}
__device__ __forceinline__ uint2 lds64(uint32_t addr) {
    uint2 v;
    asm volatile("ld.shared.v2.b32 {%0,%1}, [%2];" : "=r"(v.x), "=r"(v.y) : "r"(addr));
    return v;
}
__device__ __forceinline__ void mma16816(float* c, uint32_t a0, uint32_t a1,
                                         uint32_t a2, uint32_t a3,
                                         uint32_t b0, uint32_t b1) {
    asm volatile(
        "mma.sync.aligned.m16n8k16.row.col.f32.f16.f16.f32 "
        "{%0,%1,%2,%3}, {%4,%5,%6,%7}, {%8,%9}, {%0,%1,%2,%3};"
        : "+f"(c[0]), "+f"(c[1]), "+f"(c[2]), "+f"(c[3])
        : "r"(a0), "r"(a1), "r"(a2), "r"(a3), "r"(b0), "r"(b1));
}

// ---------------- weight prep: fused filters, fp16, lane-contiguous fragments ----
//  t0:  wc[j] = w[3j]
//  d1:  [-w2, w2-w5, w5-w8, w8-w11, w11]
//  d2:  [-w1, w1-w4, w4-w7, w7-w10, w10]
__global__ void pack_w(const float* __restrict__ w) {
    int o = blockIdx.x;      // 0..255
    int c = threadIdx.x;     // 0..63 (input channel within group)
    int g = o >> 6, oo = o & 63;
    const float* ws = w + ((size_t)o * 64 + c) * 13;
    float f[3][5];
    #pragma unroll
    for (int j = 0; j < 5; j++) f[0][j] = ws[3 * j];
    f[1][0] = -ws[2];  f[1][1] = ws[2] - ws[5];  f[1][2] = ws[5] - ws[8];
    f[1][3] = ws[8] - ws[11];  f[1][4] = ws[11];
    f[2][0] = -ws[1];  f[2][1] = ws[1] - ws[4];  f[2][2] = ws[4] - ws[7];
    f[2][3] = ws[7] - ws[10];  f[2][4] = ws[10];

    // channel c -> (cblk, q, hi, sub); mma b-frag word hi at k-word wl = cblk*8 + hi*4 + q
    int wl = c >> 1, sub = c & 1;
    int q = wl & 3, hi = (wl >> 2) & 1, cblk = wl >> 3;
    char* base = (char*)g_wB + (size_t)g * B_PER_G;
    #pragma unroll
    for (int fi = 0; fi < 3; fi++) {
        int n = fi * 64 + oo;            // B row 0..191
        int wn = n / 48;
        int rem = n - wn * 48;
        int ni = rem >> 3, ls = rem & 7;
        int lane = ls * 4 + q;
        size_t off = (size_t)cblk * B_PER_JC + (size_t)wn * (32 * 48)
                   + (size_t)lane * 48 + ni * 8 + hi * 4 + sub * 2;
        #pragma unroll
        for (int j = 0; j < 5; j++)
            *(__half*)(base + (size_t)j * B_PER_J + off) = __float2half_rn(f[fi][j]);
    }
}

// ---------------- main kernel ----------------
// grid (137, 16, 4), 256 threads, 3 CTAs/SM. Per-phase CTAs.
// Warp (wm = wid&1, wn = wid>>1): rows wm*32..+31 of 64, cols wn*48..+47 of 192.
// Tile row m <-> t = tbase + m - 2; A[m,(j,c)] = xs[tbase + m - 4 + j][c].
__global__ void __launch_bounds__(256, 3) pconv_mma(
    const float* __restrict__ x, const float* __restrict__ bias, float* __restrict__ out)
{
    extern __shared__ char smem[];
    const uint32_t sb = smem_u32(smem);
    const int tid = threadIdx.x, lane = tid & 31, wid = tid >> 5;
    const int wm = wid & 1, wn = wid >> 1;
    const int q = lane & 3, ls = lane >> 2;
    const int tbase = blockIdx.x * TSTRIDE;
    const int batch = blockIdx.y >> 1, phase = blockIdx.y & 1;
    const int g = blockIdx.z;

    // per-lane B base pointer (lane-contiguous 48B fragments)
    const char* bp0 = (const char*)g_wB + (size_t)g * B_PER_G
                    + (size_t)wn * (32 * 48) + (size_t)lane * 48;

    // ---- stage x tile: rows p = tbase-4+m, fp16, swizzled pair layout ----
    {
        uint32_t* xw = (uint32_t*)smem;
        const float* xg = x + ((size_t)batch * 256 + (size_t)g * 64) * TFULL + phase;
        const int i0 = wid;          // channel-pair base 0..7
        const int ml = lane;
        #pragma unroll
        for (int ib = 0; ib < 4; ib++) {
            int i = i0 + ib * 8;     // channel pair 0..31
            int iq = i & 3, ih = (i >> 2) & 1, icb = i >> 3;
            const float* xr0 = xg + (size_t)(2 * i) * TFULL;
            const float* xr1 = xg + (size_t)(2 * i + 1) * TFULL;
            #pragma unroll
            for (int mb = 0; mb < 3; mb++) {
                int m = ml + mb * 32;
                if (m >= XR) break;
                int p = tbase - 4 + m;
                float v0 = 0.f, v1 = 0.f;
                if (p >= 0 && p < TI) {
                    v0 = xr0[2 * (size_t)p];
                    v1 = xr1[2 * (size_t)p];
                }
                __half h0 = __float2half_rn(v0), h1 = __float2half_rn(v1);
                int pw = icb * 8 + 2 * (iq ^ swz(m)) + ih;
                xw[m * XPW + pw] = (uint32_t)__half_as_ushort(h0)
                                 | ((uint32_t)__half_as_ushort(h1) << 16);
            }
        }
    }

    float acc[2][6][4];
    #pragma unroll
    for (int mi = 0; mi < 2; mi++)
        #pragma unroll
        for (int ni = 0; ni < 6; ni++)
            #pragma unroll
            for (int k = 0; k < 4; k++) acc[mi][ni][k] = 0.f;

    __syncthreads();   // x tile visible; mainloop is sync-free

    #pragma unroll
    for (int j = 0; j < 5; j++) {
        #pragma unroll
        for (int cblk = 0; cblk < 4; cblk++) {
            // B fragments: 3 x LDG.128 = 6 uint2 frags (L1-resident image)
            const uint4* bp = (const uint4*)(bp0 + (size_t)j * B_PER_J
                                                 + (size_t)cblk * B_PER_JC);
            uint4 u0 = __ldg(bp);
            uint4 u1 = __ldg(bp + 1);
            uint4 u2 = __ldg(bp + 2);

            uint2 a[2][2];
            #pragma unroll
            for (int mi = 0; mi < 2; mi++)
                #pragma unroll
                for (int ro = 0; ro < 2; ro++) {
                    int r = wm * 32 + mi * 16 + ls + j + ro * 8;
                    uint32_t woff = (uint32_t)(r * XPW + cblk * 8 + 2 * (q ^ swz(r))) * 4;
                    a[mi][ro] = lds64(sb + woff);
                }

            #pragma unroll
            for (int mi = 0; mi < 2; mi++) {
                mma16816(acc[mi][0], a[mi][0].x, a[mi][1].x, a[mi][0].y, a[mi][1].y, u0.x, u0.y);
                mma16816(acc[mi][1], a[mi][0].x, a[mi][1].x, a[mi][0].y, a[mi][1].y, u0.z, u0.w);
                mma16816(acc[mi][2], a[mi][0].x, a[mi][1].x, a[mi][0].y, a[mi][1].y, u1.x, u1.y);
                mma16816(acc[mi][3], a[mi][0].x, a[mi][1].x, a[mi][0].y, a[mi][1].y, u1.z, u1.w);
                mma16816(acc[mi][4], a[mi][0].x, a[mi][1].x, a[mi][0].y, a[mi][1].y, u2.x, u2.y);
                mma16816(acc[mi][5], a[mi][0].x, a[mi][1].x, a[mi][0].y, a[mi][1].y, u2.z, u2.w);
            }
        }
    }

    // ---- epilogue: dump acc -> smem [64][195] f32 (overlays x tile) ----
    __syncthreads();
    float* eb = (float*)smem;
    #pragma unroll
    for (int mi = 0; mi < 2; mi++) {
        int r0 = wm * 32 + mi * 16 + ls;
        #pragma unroll
        for (int ni = 0; ni < 6; ni++) {
            int col = wn * 48 + ni * 8 + q * 2;
            eb[r0 * EPITCH + col]           = acc[mi][ni][0];
            eb[r0 * EPITCH + col + 1]       = acc[mi][ni][1];
            eb[(r0 + 8) * EPITCH + col]     = acc[mi][ni][2];
            eb[(r0 + 8) * EPITCH + col + 1] = acc[mi][ni][3];
        }
    }
    __syncthreads();

    const bool interior = (blockIdx.x > 0) && (blockIdx.x < NT - 1);
    float* outg = out + ((size_t)batch * 256 + (size_t)g * 64) * TFULL + phase;

    if (interior) {
        #pragma unroll 1
        for (int ko = 0; ko < 8; ko++) {
            int o = wid * 8 + ko;
            float bv = __ldg(&bias[g * 64 + o]);
            float* op = outg + (size_t)o * TFULL;
            #pragma unroll
            for (int rb = 0; rb < 2; rb++) {
                int m = 2 + rb * 32 + lane;
                if (m > 61) continue;
                int t = tbase + m - 2;
                float s0 = eb[(m - 2) * EPITCH + o] + bv;
                float s1 = eb[(m - 1) * EPITCH + o] + bv;
                float s2 = eb[m * EPITCH + o] + bv;
                float s3 = eb[(m + 1) * EPITCH + o] + bv;
                float s4 = eb[(m + 2) * EPITCH + o] + bv;
                float mean = (s0 + s1 + s2 + s3 + s4) * 0.2f;
                float den = fminf(fmaxf(s2 - mean, 1.0f), BOUND);
                float y = fmaf(den, -0.70710678f, 1.6944272f);
                y = y * (2.0f - den * y);
                y = y * (2.0f - den * y);
                float d1 = eb[m * EPITCH + 64 + o];
                float d2 = eb[m * EPITCH + 128 + o];
                float r = 0.25f * (s2 + (d1 + d2) * y + 2.0f * (d2 - d1) * y * y);
                op[2 * (size_t)t] = r;
            }
        }
    } else {
        #pragma unroll 1
        for (int ko = 0; ko < 8; ko++) {
            int o = wid * 8 + ko;
            float bv = __ldg(&bias[g * 64 + o]);
            float* op = outg + (size_t)o * TFULL;
            #pragma unroll 1
            for (int rb = 0; rb < 2; rb++) {
                int m = 2 + rb * 32 + lane;
                if (m > 61) continue;
                int t = tbase + m - 2;
                if (t >= TI) continue;
                float s[5];
                #pragma unroll
                for (int d = 0; d < 5; d++) {
                    int rm = m - 2 + d;
                    int tr = tbase + rm - 2;
                    float v = eb[rm * EPITCH + o] + bv;
                    s[d] = (tr >= 2 && tr < TI - 2) ? v : 0.f;
                }
                float mean = (s[0] + s[1] + s[2] + s[3] + s[4]) * 0.2f;
                float den = fminf(fmaxf(s[2] - mean, 1.0f), BOUND);
                float y = fmaf(den, -0.70710678f, 1.6944272f);
                y = y * (2.0f - den * y);
                y = y * (2.0f - den * y);
                bool cv = (t >= 2) && (t < TI - 2);
                float d1 = cv ? eb[m * EPITCH + 64 + o]  : 0.f;
                float d2 = cv ? eb[m * EPITCH + 128 + o] : 0.f;
                float r = 0.25f * (s[2] + (d1 + d2) * y + 2.0f * (d2 - d1) * y * y);
                op[2 * (size_t)t] = r;
            }
        }
    }
}

extern "C" void kernel_launch(void* const* d_in, const int* in_sizes, int n_in,
                              void* d_out, int out_size)
{
    const float* x = (const float*)d_in[0];
    const float* w = (const float*)d_in[1];
    const float* b = (const float*)d_in[2];
    float* out = (float*)d_out;

    pack_w<<<256, 64>>>(w);

    cudaFuncSetAttribute(pconv_mma, cudaFuncAttributeMaxDynamicSharedMemorySize, SMEMSZ);
    dim3 grid(NT, 16, 4);
    pconv_mma<<<grid, 256, SMEMSZ>>>(x, b, out);
}